// round 2
// baseline (speedup 1.0000x reference)
#include <cuda_runtime.h>
#include <cuda_bf16.h>
#include <cstdint>

// Problem constants (shapes fixed by setup_inputs)
#define HW      (1024 * 1024)             // pixels per channel
#define NBINS   16
#define NTOT    (NBINS * NBINS * NBINS)   // 4096
#define NPAIR   (NTOT / 2)                // 2048 paired (64-bit) bins
#define NIMG    9                         // 8 input images + 1 style image
#define BPI     64                        // blocks per image
#define TPB     256                       // threads per block
#define NCTA    (BPI * NIMG)              // 576 CTAs total

// Global scratch (zero-initialized at module load; last CTA re-zeros each run).
// Each 64-bit word packs two adjacent 32-bit bin counts.
__device__ unsigned long long g_hist2[NIMG][NPAIR];
__device__ unsigned int       g_done;

// searchsorted(boundaries, v, side='left') with boundaries = i/8 - 1, i=1..15.
// = count of boundaries strictly < v = clamp(ceil(8*(v+1)) - 1, 0, 15).
__device__ __forceinline__ int bin_of(float v) {
    float t = (v + 1.0f) * 8.0f;
    int i = (int)ceilf(t) - 1;
    i = i < 0 ? 0 : i;
    i = i > 15 ? 15 : i;
    return i;
}

__device__ __forceinline__ int flat_bin(float r, float g, float b) {
    return bin_of(r) + (bin_of(g) << 4) + (bin_of(b) << 8);
}

// ---------------------------------------------------------------------------
// Single fused kernel: histogram + global flush + last-CTA loss + state reset.
// grid = (BPI, NIMG), block = TPB.
// ---------------------------------------------------------------------------
__global__ __launch_bounds__(TPB) void fused_colorloss_kernel(
    const float* __restrict__ inp,   // [8, 3, H, W]
    const float* __restrict__ sty,   // [1, 3, H, W]
    float* __restrict__ out)         // [1]
{
    __shared__ int sh[NTOT];         // 16 KB per-CTA histogram
    #pragma unroll
    for (int i = threadIdx.x; i < NTOT; i += TPB) sh[i] = 0;
    __syncthreads();

    const int img = blockIdx.y;
    const float* base = (img < 8) ? (inp + (size_t)img * 3 * HW) : sty;

    const float4* r4 = (const float4*)(base);
    const float4* g4 = (const float4*)(base + HW);
    const float4* b4 = (const float4*)(base + 2 * HW);

    const int per_block = (HW / 4) / BPI;          // 4096 float4 per channel
    const int start     = blockIdx.x * per_block;
    const int end       = start + per_block;

    #pragma unroll 2
    for (int i = start + threadIdx.x; i < end; i += TPB) {
        float4 r = __ldcs(&r4[i]);
        float4 g = __ldcs(&g4[i]);
        float4 b = __ldcs(&b4[i]);

        int f0 = flat_bin(r.x, g.x, b.x);
        int f1 = flat_bin(r.y, g.y, b.y);
        int f2 = flat_bin(r.z, g.z, b.z);
        int f3 = flat_bin(r.w, g.w, b.w);

        atomicAdd(&sh[f0], 1);
        atomicAdd(&sh[f1], 1);
        atomicAdd(&sh[f2], 1);
        atomicAdd(&sh[f3], 1);
    }
    __syncthreads();

    // Flush: pack two adjacent bins into one 64-bit atomic (counts < 2^32).
    #pragma unroll
    for (int i = threadIdx.x; i < NPAIR; i += TPB) {
        unsigned int lo = (unsigned int)sh[2 * i];
        unsigned int hi = (unsigned int)sh[2 * i + 1];
        if (lo | hi) {
            atomicAdd(&g_hist2[img][i],
                      (unsigned long long)lo | ((unsigned long long)hi << 32));
        }
    }

    // --- last-CTA detection (threadfence-reduction pattern) ---
    __threadfence();
    __syncthreads();
    __shared__ int is_last;
    if (threadIdx.x == 0) {
        unsigned int ticket = atomicAdd(&g_done, 1u);
        is_last = (ticket == (unsigned int)(NCTA - 1));
    }
    __syncthreads();
    if (!is_last) return;

    // --- last CTA: exact integer L1 loss ---
    // Reuse sh[] to cache the unpacked style histogram.
    #pragma unroll
    for (int i = threadIdx.x; i < NPAIR; i += TPB) {
        unsigned long long p = __ldcg(&g_hist2[8][i]);
        sh[2 * i]     = (int)(unsigned int)(p & 0xffffffffULL);
        sh[2 * i + 1] = (int)(unsigned int)(p >> 32);
    }
    __syncthreads();

    int acc = 0;   // max possible sum = 2*8*HW = 16.8M < 2^31
    #pragma unroll 1
    for (int b = 0; b < 8; b++) {
        for (int i = threadIdx.x; i < NPAIR; i += TPB) {
            unsigned long long p = __ldcg(&g_hist2[b][i]);
            int d0 = (int)(unsigned int)(p & 0xffffffffULL) - sh[2 * i];
            int d1 = (int)(unsigned int)(p >> 32)           - sh[2 * i + 1];
            acc += (d0 < 0 ? -d0 : d0) + (d1 < 0 ? -d1 : d1);
        }
    }

    // block reduction
    #pragma unroll
    for (int o = 16; o > 0; o >>= 1)
        acc += __shfl_xor_sync(0xffffffffu, acc, o);

    __shared__ int warp_sum[TPB / 32];
    if ((threadIdx.x & 31) == 0) warp_sum[threadIdx.x >> 5] = acc;
    __syncthreads();

    if (threadIdx.x == 0) {
        long long total = 0;
        #pragma unroll
        for (int w = 0; w < TPB / 32; w++) total += warp_sum[w];
        out[0] = (float)((double)total /
                         ((double)HW * 8.0 * (double)NTOT));
    }

    // --- reset scratch for the next graph replay ---
    __syncthreads();
    unsigned long long* flat = (unsigned long long*)g_hist2;
    #pragma unroll
    for (int i = threadIdx.x; i < NIMG * NPAIR; i += TPB) flat[i] = 0ULL;
    if (threadIdx.x == 0) g_done = 0u;
}

// ---------------------------------------------------------------------------
// Launch contract
// ---------------------------------------------------------------------------
extern "C" void kernel_launch(void* const* d_in, const int* in_sizes, int n_in,
                              void* d_out, int out_size)
{
    const float* inp = (const float*)d_in[0];   // [8,3,1024,1024] fp32
    const float* sty = (const float*)d_in[1];   // [1,3,1024,1024] fp32
    float* out = (float*)d_out;

    dim3 grid(BPI, NIMG);
    fused_colorloss_kernel<<<grid, TPB>>>(inp, sty, out);
}